// round 1
// baseline (speedup 1.0000x reference)
#include <cuda_runtime.h>
#include <cuda_bf16.h>
#include <math.h>

// DWT1D: x [B, N, C] f32, A [N, N] banded 2-tap analysis filter bank
// (periodic). out [B, N/2, 2C]: lowpass band in channels [0,C),
// highpass band in channels [C,2C).
//
// Linear-offset identity: out[b,k,c]        <-> x[b,2k,c]   (same offset)
//                         out[b,k,C+c]      <-> x[b,2k+1,c] (same offset)
// => pure in-place-indexed streaming kernel, fully coalesced.
//
// Filter taps read from A: h0 = (A[0,0], A[0,1]), h1 = (A[N/2,0], A[N/2,1]).

__global__ void __launch_bounds__(256) dwt1d_haar_stream(
    const float4* __restrict__ x,
    const float*  __restrict__ A,
    float4*       __restrict__ out,
    int n_threads,            // total float4-pairs to process
    size_t half_row_off)      // (N/2)*N : offset of first highpass row in A
{
    int idx = blockIdx.x * blockDim.x + threadIdx.x;
    if (idx >= n_threads) return;

    // 4 broadcast loads; L1/L2 resident after first sector fetch.
    const float h00 = __ldg(&A[0]);
    const float h01 = __ldg(&A[1]);
    const float h10 = __ldg(&A[half_row_off]);
    const float h11 = __ldg(&A[half_row_off + 1]);

    // Each "pair" = one (even row, odd row) of 64 channels = 128 floats
    // = 32 float4. Thread handles float4-column c (0..15) of one pair.
    const int pair = idx >> 4;
    const int c    = idx & 15;
    const size_t base = (size_t)pair * 32 + c;   // in float4 units

    const float4 a = x[base];        // x[b, 2k,   4c:4c+4]
    const float4 b = x[base + 16];   // x[b, 2k+1, 4c:4c+4]

    float4 lo, hi;
    lo.x = a.x * h00 + b.x * h01;
    lo.y = a.y * h00 + b.y * h01;
    lo.z = a.z * h00 + b.z * h01;
    lo.w = a.w * h00 + b.w * h01;

    hi.x = a.x * h10 + b.x * h11;
    hi.y = a.y * h10 + b.y * h11;
    hi.z = a.z * h10 + b.z * h11;
    hi.w = a.w * h10 + b.w * h11;

    out[base]      = lo;   // lowpass  -> out[b, k, 4c:4c+4]
    out[base + 16] = hi;   // highpass -> out[b, k, C+4c : C+4c+4]
}

extern "C" void kernel_launch(void* const* d_in, const int* in_sizes, int n_in,
                              void* d_out, int out_size)
{
    const float* x = (const float*)d_in[0];   // [B, N, C] f32
    const float* A = (const float*)d_in[1];   // [N, N]    f32
    float* out = (float*)d_out;               // [B, N/2, 2C] f32

    // N from A's element count (N*N).
    long long a_elems = (long long)in_sizes[1];
    int N = (int)llround(sqrt((double)a_elems));
    size_t half_row_off = (size_t)(N / 2) * (size_t)N;

    // Total floats in x == total floats in out; each thread moves 8 floats.
    long long total = (long long)in_sizes[0];
    int n_threads = (int)(total / 8);

    const int TPB = 256;
    int blocks = (n_threads + TPB - 1) / TPB;

    dwt1d_haar_stream<<<blocks, TPB>>>(
        (const float4*)x, A, (float4*)out, n_threads, half_row_off);
}